// round 1
// baseline (speedup 1.0000x reference)
#include <cuda_runtime.h>

#define N_NODES 100000
#define N_EDGES 3200000
#define F_IN    1433
#define F_HID   16
#define F_OUT   7

// ---------------- scratch (device globals; no allocation allowed) ----------
__device__ float g_h1  [N_NODES * F_HID];   // 6.4 MB  (ns-scaled X @ W1)
__device__ float g_agg1[N_NODES * F_HID];   // 6.4 MB  scatter target layer 1
__device__ float g_h2  [N_NODES * 8];       // 3.2 MB  (padded to 8 for v4 red)
__device__ float g_agg2[N_NODES * 8];       // 3.2 MB  scatter target layer 2
__device__ float g_degout[N_NODES];
__device__ float g_degin [N_NODES];
__device__ float g_ns[N_NODES];
__device__ float g_nd[N_NODES];

__device__ __forceinline__ void red_add_v4(float* p, float4 v) {
    asm volatile("red.global.add.v4.f32 [%0], {%1, %2, %3, %4};"
                 :: "l"(p), "f"(v.x), "f"(v.y), "f"(v.z), "f"(v.w)
                 : "memory");
}

// ---------------- zeroing (graph-replay safe) -------------------------------
__global__ void zero_kernel() {
    int t = blockIdx.x * blockDim.x + threadIdx.x;
    float4 z = make_float4(0.f, 0.f, 0.f, 0.f);
    if (t < N_NODES * F_HID / 4) ((float4*)g_agg1)[t] = z;
    if (t < N_NODES * 8 / 4)     ((float4*)g_agg2)[t] = z;
    if (t < N_NODES) { g_degout[t] = 0.f; g_degin[t] = 0.f; }
}

// ---------------- degrees + norms -------------------------------------------
__global__ void degree_kernel(const int* __restrict__ src,
                              const int* __restrict__ dst) {
    int e = blockIdx.x * blockDim.x + threadIdx.x;
    if (e >= N_EDGES) return;
    atomicAdd(&g_degout[src[e]], 1.0f);
    atomicAdd(&g_degin [dst[e]], 1.0f);
}

__global__ void norm_kernel() {
    int n = blockIdx.x * blockDim.x + threadIdx.x;
    if (n >= N_NODES) return;
    g_ns[n] = rsqrtf(fmaxf(g_degout[n], 1.0f));
    g_nd[n] = rsqrtf(fmaxf(g_degin [n], 1.0f));
}

// ---------------- GEMM1: h1 = diag(ns) * X @ W1  [100000 x 1433 x 16] -------
// One warp owns 4 rows. Lanes split K (coalesced X loads, 128B/row/iter).
// W rows (16 floats = 4 x float4) read straight from gmem: whole W1 (92 KB)
// is L1-resident, so these are L1 hits. 64 FFMA per k-step per warp -> the
// kernel is FFMA-issue bound, which is the fp32 roofline for this shape.
__global__ __launch_bounds__(256) void gemm1_kernel(const float* __restrict__ X,
                                                    const float* __restrict__ W) {
    int gwarp = (blockIdx.x * 256 + threadIdx.x) >> 5;
    int lane  = threadIdx.x & 31;
    long m0 = (long)gwarp * 4;
    if (m0 >= N_NODES) return;

    float4 acc[4][4];
#pragma unroll
    for (int i = 0; i < 4; i++)
#pragma unroll
        for (int j = 0; j < 4; j++) acc[i][j] = make_float4(0.f, 0.f, 0.f, 0.f);

    const float4* W4  = (const float4*)W;
    const float*  Xr  = X + m0 * F_IN;

    int k0 = 0;
#pragma unroll 2
    for (; k0 + 32 <= F_IN; k0 += 32) {
        int k = k0 + lane;
        float xv[4];
#pragma unroll
        for (int i = 0; i < 4; i++) xv[i] = Xr[(long)i * F_IN + k];
        float4 w[4];
#pragma unroll
        for (int j = 0; j < 4; j++) w[j] = W4[k * 4 + j];
#pragma unroll
        for (int i = 0; i < 4; i++)
#pragma unroll
            for (int j = 0; j < 4; j++) {
                acc[i][j].x = fmaf(xv[i], w[j].x, acc[i][j].x);
                acc[i][j].y = fmaf(xv[i], w[j].y, acc[i][j].y);
                acc[i][j].z = fmaf(xv[i], w[j].z, acc[i][j].z);
                acc[i][j].w = fmaf(xv[i], w[j].w, acc[i][j].w);
            }
    }
    { // K tail (1433 = 44*32 + 25)
        int k = k0 + lane;
        float xv[4] = {0.f, 0.f, 0.f, 0.f};
        float4 w[4];
#pragma unroll
        for (int j = 0; j < 4; j++) w[j] = make_float4(0.f, 0.f, 0.f, 0.f);
        if (k < F_IN) {
#pragma unroll
            for (int i = 0; i < 4; i++) xv[i] = Xr[(long)i * F_IN + k];
#pragma unroll
            for (int j = 0; j < 4; j++) w[j] = W4[k * 4 + j];
        }
#pragma unroll
        for (int i = 0; i < 4; i++)
#pragma unroll
            for (int j = 0; j < 4; j++) {
                acc[i][j].x = fmaf(xv[i], w[j].x, acc[i][j].x);
                acc[i][j].y = fmaf(xv[i], w[j].y, acc[i][j].y);
                acc[i][j].z = fmaf(xv[i], w[j].z, acc[i][j].z);
                acc[i][j].w = fmaf(xv[i], w[j].w, acc[i][j].w);
            }
    }

    // butterfly reduce across lanes
#pragma unroll
    for (int i = 0; i < 4; i++)
#pragma unroll
        for (int j = 0; j < 4; j++)
#pragma unroll
            for (int off = 16; off > 0; off >>= 1) {
                acc[i][j].x += __shfl_xor_sync(0xffffffffu, acc[i][j].x, off);
                acc[i][j].y += __shfl_xor_sync(0xffffffffu, acc[i][j].y, off);
                acc[i][j].z += __shfl_xor_sync(0xffffffffu, acc[i][j].z, off);
                acc[i][j].w += __shfl_xor_sync(0xffffffffu, acc[i][j].w, off);
            }

    if (lane == 0) {
#pragma unroll
        for (int i = 0; i < 4; i++) {
            float s = g_ns[m0 + i];
            float4* o = (float4*)(g_h1 + (m0 + i) * F_HID);
#pragma unroll
            for (int j = 0; j < 4; j++) {
                float4 v = acc[i][j];
                v.x *= s; v.y *= s; v.z *= s; v.w *= s;
                o[j] = v;
            }
        }
    }
}

// ---------------- scatter 1: agg1[dst] += h1[src]  (16 wide) ----------------
__global__ void scatter1_kernel(const int* __restrict__ src,
                                const int* __restrict__ dst) {
    int e = blockIdx.x * blockDim.x + threadIdx.x;
    if (e >= N_EDGES) return;
    int s = src[e], d = dst[e];
    const float4* hs = (const float4*)(g_h1 + (size_t)s * F_HID);
    float4 a = hs[0], b = hs[1], c = hs[2], f = hs[3];
    float* base = g_agg1 + (size_t)d * F_HID;
    red_add_v4(base + 0,  a);
    red_add_v4(base + 4,  b);
    red_add_v4(base + 8,  c);
    red_add_v4(base + 12, f);
}

// ---------------- GEMM2: h2 = diag(ns) * relu(agg1*nd + b1) @ W2 ------------
__global__ void gemm2_kernel(const float* __restrict__ b1,
                             const float* __restrict__ W2) {
    __shared__ float sW[F_HID * F_OUT];
    __shared__ float sb[F_HID];
    if (threadIdx.x < F_HID * F_OUT) sW[threadIdx.x] = W2[threadIdx.x];
    if (threadIdx.x < F_HID)         sb[threadIdx.x] = b1[threadIdx.x];
    __syncthreads();

    int n = blockIdx.x * blockDim.x + threadIdx.x;
    if (n >= N_NODES) return;

    float ndv = g_nd[n], nsv = g_ns[n];
    const float4* a4 = (const float4*)(g_agg1 + (size_t)n * F_HID);
    float x[F_HID];
#pragma unroll
    for (int q = 0; q < 4; q++) {
        float4 v = a4[q];
        x[q*4+0] = v.x; x[q*4+1] = v.y; x[q*4+2] = v.z; x[q*4+3] = v.w;
    }
    float o[F_OUT];
#pragma unroll
    for (int j = 0; j < F_OUT; j++) o[j] = 0.f;
#pragma unroll
    for (int i = 0; i < F_HID; i++) {
        float xi = fmaxf(fmaf(x[i], ndv, sb[i]), 0.f) * nsv;
#pragma unroll
        for (int j = 0; j < F_OUT; j++) o[j] = fmaf(xi, sW[i * F_OUT + j], o[j]);
    }
    float4* hp = (float4*)(g_h2 + (size_t)n * 8);
    hp[0] = make_float4(o[0], o[1], o[2], o[3]);
    hp[1] = make_float4(o[4], o[5], o[6], 0.f);   // pad lane stays 0
}

// ---------------- scatter 2: agg2[dst] += h2[src]  (8 wide, padded) ---------
__global__ void scatter2_kernel(const int* __restrict__ src,
                                const int* __restrict__ dst) {
    int e = blockIdx.x * blockDim.x + threadIdx.x;
    if (e >= N_EDGES) return;
    int s = src[e], d = dst[e];
    const float4* hs = (const float4*)(g_h2 + (size_t)s * 8);
    float4 a = hs[0], b = hs[1];
    float* base = g_agg2 + (size_t)d * 8;
    red_add_v4(base + 0, a);
    red_add_v4(base + 4, b);
}

// ---------------- finalize: out = agg2*nd + b2 -------------------------------
__global__ void final_kernel(const float* __restrict__ b2,
                             float* __restrict__ out) {
    int t = blockIdx.x * blockDim.x + threadIdx.x;
    if (t >= N_NODES * F_OUT) return;
    int n = t / F_OUT;
    int j = t - n * F_OUT;
    out[t] = fmaf(g_agg2[(size_t)n * 8 + j], g_nd[n], b2[j]);
}

// ---------------- launch ------------------------------------------------------
extern "C" void kernel_launch(void* const* d_in, const int* in_sizes, int n_in,
                              void* d_out, int out_size) {
    const float* X   = (const float*)d_in[0];
    const int*   src = (const int*)  d_in[1];
    const int*   dst = (const int*)  d_in[2];
    const float* W1  = (const float*)d_in[3];
    const float* b1  = (const float*)d_in[4];
    const float* W2  = (const float*)d_in[5];
    const float* b2  = (const float*)d_in[6];
    float* out = (float*)d_out;

    zero_kernel  <<<(N_NODES * F_HID / 4 + 255) / 256, 256>>>();
    degree_kernel<<<N_EDGES / 256, 256>>>(src, dst);
    norm_kernel  <<<(N_NODES + 255) / 256, 256>>>();
    gemm1_kernel <<<N_NODES / 32, 256>>>(X, W1);          // 3125 blocks, 8 warps x 4 rows
    scatter1_kernel<<<N_EDGES / 256, 256>>>(src, dst);
    gemm2_kernel <<<(N_NODES + 255) / 256, 256>>>(b1, W2);
    scatter2_kernel<<<N_EDGES / 256, 256>>>(src, dst);
    final_kernel <<<(N_NODES * F_OUT + 255) / 256, 256>>>(b2, out);
}